// round 14
// baseline (speedup 1.0000x reference)
#include <cuda_runtime.h>
#include <cuda_fp16.h>
#include <math.h>
#include <stdint.h>

#define BATCH 8
#define NPTS  4096
#define DIM   64
#define TILE  128
#define NT    (NPTS / TILE)            // 32
#define NTRI  (NT * (NT + 1) / 2)      // 528 upper-tri tiles per batch
#define SLOTS 37                       // CTAs per batch
#define GRID  (BATCH * SLOTS)          // 296
#define TPB   256

// smem sub-tile: 128 rows x 72 fp16 (144 B stride) -> conflict-free ldmatrix/STS
#define SROWB   144
#define SUBTILE (128 * SROWB)          // 18432 B
#define BUFSZ   (2 * SUBTILE)          // A+B = 36864 B
#define NBUF    3                      // triple buffer -> single barrier per tile
#define SMEM_BYTES (NBUF * BUFSZ)      // 110592 (2 CTAs/SM)

// Both operands from ONE array scaled by sqrt(0.5*log2(e)):
// (s*a)·(s*b) = 0.5*log2(e)*a·b  ->  ex2(acc) = exp(0.5*<a,b>)
__device__ __align__(16) __half g_s[BATCH * NPTS * DIM];
__device__ double g_partials[GRID];
__device__ unsigned g_cnt = 0;

__device__ __forceinline__ uint32_t smem_u32(const void* p) {
    uint32_t a;
    asm("{ .reg .u64 t; cvta.to.shared.u64 t, %1; cvt.u32.u64 %0, t; }" : "=r"(a) : "l"(p));
    return a;
}
template <int IMM>
__device__ __forceinline__ void ldsm4i(uint32_t* r, uint32_t addr) {
    asm volatile("ldmatrix.sync.aligned.m8n8.x4.shared.b16 {%0,%1,%2,%3}, [%4+%5];"
                 : "=r"(r[0]), "=r"(r[1]), "=r"(r[2]), "=r"(r[3])
                 : "r"(addr), "n"(IMM));
}
// NON-volatile MMA: ordering pinned by register dependencies only.
__device__ __forceinline__ void mma_acc(float* d, const uint32_t* a, const uint32_t* b) {
    asm("mma.sync.aligned.m16n8k16.row.col.f32.f16.f16.f32 "
        "{%0,%1,%2,%3}, {%4,%5,%6,%7}, {%8,%9}, {%0,%1,%2,%3};"
        : "+f"(d[0]), "+f"(d[1]), "+f"(d[2]), "+f"(d[3])
        : "r"(a[0]), "r"(a[1]), "r"(a[2]), "r"(a[3]), "r"(b[0]), "r"(b[1]));
}
// first-use variant: C = 0 -> writes acc fresh, no zeroing MOVs needed.
__device__ __forceinline__ void mma_zro(float* d, const uint32_t* a, const uint32_t* b) {
    asm("mma.sync.aligned.m16n8k16.row.col.f32.f16.f16.f32 "
        "{%0,%1,%2,%3}, {%4,%5,%6,%7}, {%8,%9}, {%10,%10,%10,%10};"
        : "=f"(d[0]), "=f"(d[1]), "=f"(d[2]), "=f"(d[3])
        : "r"(a[0]), "r"(a[1]), "r"(a[2]), "r"(a[3]), "r"(b[0]), "r"(b[1]), "f"(0.0f));
}
template <int DI, int SI>
__device__ __forceinline__ void cp16i(uint32_t dst, const __half* src) {
    asm volatile("cp.async.ca.shared.global [%0+%2], [%1+%3], 16;"
                 :: "r"(dst), "l"(src), "n"(DI), "n"(SI));
}
__device__ __forceinline__ float ex2f(float x) {
    float e;
    asm("ex2.approx.f32 %0, %1;" : "=f"(e) : "f"(x));
    return e;
}

// ---------------- 1) convert f32 -> fp16 scaled by sqrt(0.5*log2e) ----------------
__global__ __launch_bounds__(256) void split_kernel(const float* __restrict__ emb) {
    const float SQC = 0.84932180612318867f;  // sqrt(0.5*log2(e))
    int i = (blockIdx.x * 256 + threadIdx.x) * 4;
    float4 v = *(const float4*)(emb + i);
    float x[4] = {v.x, v.y, v.z, v.w};
    __half s[4];
    #pragma unroll
    for (int j = 0; j < 4; ++j) s[j] = __float2half(x[j] * SQC);
    *(uint2*)&g_s[i] = *(uint2*)s;
}

// ---------------- 2) persistent HMMA tile kernel (fused finalize) ----------------
__device__ __forceinline__ void load_tile(uint32_t dstA, const __half* sA, const __half* sB,
                                          bool dg) {
    cp16i<0 * SROWB, 0 * DIM * 2>(dstA, sA);
    cp16i<32 * SROWB, 32 * DIM * 2>(dstA, sA);
    cp16i<64 * SROWB, 64 * DIM * 2>(dstA, sA);
    cp16i<96 * SROWB, 96 * DIM * 2>(dstA, sA);
    if (!dg) {   // diagonal tile: B region = A region, skip the B load
        cp16i<SUBTILE + 0 * SROWB, 0 * DIM * 2>(dstA, sB);
        cp16i<SUBTILE + 32 * SROWB, 32 * DIM * 2>(dstA, sB);
        cp16i<SUBTILE + 64 * SROWB, 64 * DIM * 2>(dstA, sB);
        cp16i<SUBTILE + 96 * SROWB, 96 * DIM * 2>(dstA, sB);
    }
    asm volatile("cp.async.commit_group;" ::: "memory");
}

// Segment S: accumulator groups {2S, 2S+1}, ALL 4 k-steps (k-inner, zro at k=0).
// Each acc sees every k-step of its own tile -> correct. The previous tile's
// ex2 epilogue for this pair (32 MUFU) sits at the segment head: independent of
// this segment's 32 HMMA except the per-acc overwrite order, so ptxas can
// interleave MUFU and tensor streams.
template <int S>
__device__ __forceinline__ void seg_tile(
    float acc[4][4][4], float& s0, float& s1, float& s2, float& s3,
    uint32_t aAx, uint32_t aAy, uint32_t aB0, uint32_t aB1)
{
    constexpr int M0 = 2 * S, M1 = 2 * S + 1;

    uint32_t A0[4], A1[4], B[2][4];
    ldsm4i<0>(A0, aAx); ldsm4i<0>(A1, aAy);
    ldsm4i<0>(B[0], aB0); ldsm4i<0>(B[1], aB1);

    #pragma unroll
    for (int nb = 0; nb < 4; ++nb) {
        s0 += ex2f(acc[M0][nb][0]); s1 += ex2f(acc[M0][nb][1]);
        s2 += ex2f(acc[M0][nb][2]); s3 += ex2f(acc[M0][nb][3]);
        s0 += ex2f(acc[M1][nb][0]); s1 += ex2f(acc[M1][nb][1]);
        s2 += ex2f(acc[M1][nb][2]); s3 += ex2f(acc[M1][nb][3]);
    }
    #pragma unroll
    for (int nb = 0; nb < 4; ++nb) {
        mma_zro(acc[M0][nb], A0, &B[nb >> 1][(nb & 1) * 2]);
        mma_zro(acc[M1][nb], A1, &B[nb >> 1][(nb & 1) * 2]);
    }

    #define SEG_K(KO)                                                            \
    {                                                                            \
        uint32_t A0k[4], A1k[4], Bk[2][4];                                       \
        ldsm4i<KO>(A0k, aAx); ldsm4i<KO>(A1k, aAy);                              \
        ldsm4i<KO>(Bk[0], aB0); ldsm4i<KO>(Bk[1], aB1);                          \
        _Pragma("unroll")                                                        \
        for (int nb = 0; nb < 4; ++nb) {                                         \
            mma_acc(acc[M0][nb], A0k, &Bk[nb >> 1][(nb & 1) * 2]);               \
            mma_acc(acc[M1][nb], A1k, &Bk[nb >> 1][(nb & 1) * 2]);               \
        }                                                                        \
    }
    SEG_K(32)
    SEG_K(64)
    SEG_K(96)
    #undef SEG_K
}

__global__ __launch_bounds__(TPB, 2) void tile_kernel(float* __restrict__ out) {
    extern __shared__ __align__(128) char smem[];
    __shared__ double redbuf[8];
    __shared__ int is_last_s;
    const uint32_t sbase = smem_u32(smem);
    const int tid = threadIdx.x;
    const int wid = tid >> 5;
    const int lid = tid & 31;
    const int wm = wid & 1;            // 2 warps along M (64 rows each)
    const int wn = wid >> 1;           // 4 warps along N (32 cols each)
    const bool hi = (wid >= 4);        // phase stagger: hi warps run segment 1 first

    const int bb   = blockIdx.x & 7;   // fixed batch per CTA
    const int slot = blockIdx.x >> 3;  // 0..36
    const __half* gS = g_s + (size_t)bb * NPTS * DIM;

    const int srcoff = (tid >> 3) * DIM + (tid & 7) * 8;                 // elements
    const uint32_t dsto = (uint32_t)((tid >> 3) * SROWB + (tid & 7) * 16);

    uint32_t offA[4];
    {
        int row = ((lid >> 3) & 1) * 8 + (lid & 7);
        int kc  = (lid >> 4) * 8;
        #pragma unroll
        for (int ma = 0; ma < 4; ++ma)
            offA[ma] = (uint32_t)((wm * 64 + ma * 16 + row) * SROWB + kc * 2);
    }
    uint32_t offB[2];   // WITHOUT the SUBTILE base (added per tile; diag -> A region)
    {
        int row = (lid >> 4) * 8 + (lid & 7);
        int kc  = ((lid >> 3) & 1) * 8;
        #pragma unroll
        for (int np = 0; np < 2; ++np)
            offB[np] = (uint32_t)((wn * 32 + np * 16 + row) * SROWB + kc * 2);
    }

    float facc = 0.0f;                 // running per-thread sum (all positive)
    float pw   = 0.0f;                 // weight of pending (previous) tile; 0 = none
    float acc[4][4][4];
    #pragma unroll
    for (int i = 0; i < 4; ++i)
        #pragma unroll
        for (int j = 0; j < 4; ++j)
            #pragma unroll
            for (int e = 0; e < 4; ++e) acc[i][j][e] = 0.0f;

    // Incremental triangular decode: tt = tm(tm+1)/2 + tn, 0 <= tn <= tm.
    int tn = slot, tm = 0;
    while (tn > tm) { tn -= (tm + 1); ++tm; }

    load_tile(sbase + dsto, gS + tn * (TILE * DIM) + srcoff,
              gS + tm * (TILE * DIM) + srcoff, tn == tm);

    int buf = 0;
    for (int tt = slot; tt < NTRI; tt += SLOTS) {
        const int cdiag = (tn == tm);
        const int nbuf = (buf == NBUF - 1) ? 0 : buf + 1;
        if (tt + SLOTS < NTRI) {
            tn += SLOTS;
            while (tn > tm) { tn -= (tm + 1); ++tm; }
            load_tile(sbase + nbuf * BUFSZ + dsto,
                      gS + tn * (TILE * DIM) + srcoff,
                      gS + tm * (TILE * DIM) + srcoff, tn == tm);
            asm volatile("cp.async.wait_group 1;" ::: "memory");
        } else {
            asm volatile("cp.async.wait_group 0;" ::: "memory");
        }
        __syncthreads();               // single barrier: data ready; WAR safe at depth 3

        const uint32_t bufbase = sbase + buf * BUFSZ;
        const uint32_t aA0 = bufbase + offA[0], aA1 = bufbase + offA[1];
        const uint32_t aA2 = bufbase + offA[2], aA3 = bufbase + offA[3];
        const uint32_t bB  = bufbase + (cdiag ? 0u : (uint32_t)SUBTILE);
        const uint32_t aB0 = bB + offB[0], aB1 = bB + offB[1];

        float s0 = 0.f, s1 = 0.f, s2 = 0.f, s3 = 0.f;
        if (hi) {
            seg_tile<1>(acc, s0, s1, s2, s3, aA2, aA3, aB0, aB1);
            seg_tile<0>(acc, s0, s1, s2, s3, aA0, aA1, aB0, aB1);
        } else {
            seg_tile<0>(acc, s0, s1, s2, s3, aA0, aA1, aB0, aB1);
            seg_tile<1>(acc, s0, s1, s2, s3, aA2, aA3, aB0, aB1);
        }
        facc += pw * ((s0 + s1) + (s2 + s3));  // pw=0 on first iteration

        pw = cdiag ? 1.0f : 2.0f;
        buf = nbuf;
    }

    // Final pending epilogue.
    {
        float s0 = 0.f, s1 = 0.f, s2 = 0.f, s3 = 0.f;
        #pragma unroll
        for (int ma = 0; ma < 4; ++ma)
            #pragma unroll
            for (int nb = 0; nb < 4; ++nb) {
                s0 += ex2f(acc[ma][nb][0]);
                s1 += ex2f(acc[ma][nb][1]);
                s2 += ex2f(acc[ma][nb][2]);
                s3 += ex2f(acc[ma][nb][3]);
            }
        facc += pw * ((s0 + s1) + (s2 + s3));
    }

    // One block reduction in double at the very end.
    double acc_d = (double)facc;
    #pragma unroll
    for (int o = 16; o > 0; o >>= 1)
        acc_d += __shfl_down_sync(0xffffffffu, acc_d, o);
    if (lid == 0) redbuf[wid] = acc_d;
    __syncthreads();
    if (tid == 0) {
        double v = ((redbuf[0] + redbuf[1]) + (redbuf[2] + redbuf[3])) +
                   ((redbuf[4] + redbuf[5]) + (redbuf[6] + redbuf[7]));
        g_partials[blockIdx.x] = v;
    }

    // Fused finalize: last CTA reduces per-batch and writes the loss.
    __threadfence();
    if (tid == 0) {
        unsigned o = atomicAdd(&g_cnt, 1u);
        is_last_s = (o == GRID - 1) ? 1 : 0;
    }
    __syncthreads();
    if (is_last_s) {
        __threadfence();
        const int w = wid;             // warp w handles batch w
        double s = 0.0;
        for (int i = lid; i < SLOTS; i += 32)
            s += g_partials[(i << 3) + w];
        #pragma unroll
        for (int o = 16; o > 0; o >>= 1)
            s += __shfl_down_sync(0xffffffffu, s, o);
        if (lid == 0) redbuf[w] = log(s);
        __syncthreads();
        if (tid == 0) {
            double L = ((redbuf[0] + redbuf[1]) + (redbuf[2] + redbuf[3])) +
                       ((redbuf[4] + redbuf[5]) + (redbuf[6] + redbuf[7]));
            *out = (float)(L / 8.0);
            g_cnt = 0;                 // reset for next graph replay
        }
    }
}

extern "C" void kernel_launch(void* const* d_in, const int* in_sizes, int n_in,
                              void* d_out, int out_size) {
    (void)in_sizes; (void)n_in; (void)out_size;
    const float* emb = (const float*)d_in[0];
    float* out = (float*)d_out;
    cudaFuncSetAttribute(tile_kernel, cudaFuncAttributeMaxDynamicSharedMemorySize, SMEM_BYTES);
    split_kernel<<<BATCH * NPTS * DIM / (256 * 4), 256>>>(emb);
    tile_kernel<<<GRID, TPB, SMEM_BYTES>>>(out);
}